// round 3
// baseline (speedup 1.0000x reference)
#include <cuda_runtime.h>

// Problem constants
#define NN 100000
#define NE 1600000
constexpr int IN_C = 128;
constexpr int HID  = 64;
constexpr int OUTC = 40;
constexpr float BN_EPS = 1e-5f;

constexpr int TILE = 1024;
constexpr int NTILES = (NN + TILE - 1) / TILE;   // 98

// ---------------- scratch (static device globals; no runtime alloc) -------
__device__ int   g_degcnt[NN];
__device__ float g_dis[NN];
__device__ int   g_rowptr[NN + 1];
__device__ int   g_fill[NN];
__device__ int   g_incl[NN];
__device__ int   g_tilesum[128];
__device__ int   g_tilebase[128];
__device__ int   g_csrc[NE];
__device__ float g_cw[NE];
__device__ float g_ha[NN * HID];     // gemm outputs (all layers)
__device__ float g_hb[NN * HID];     // agg outputs (layers 1,2)
__device__ float g_bn1[128];         // [0:64) sum, [64:128) sumsq
__device__ float g_bn2[128];
__device__ float g_sc1[HID], g_sh1[HID];
__device__ float g_sc2[HID], g_sh2[HID];

// ---------------- init ----------------------------------------------------
__global__ void k_init() {
    int i = blockIdx.x * blockDim.x + threadIdx.x;
    int stride = gridDim.x * blockDim.x;
    for (int j = i; j < NN; j += stride) g_degcnt[j] = 0;
    if (i < 128) { g_bn1[i] = 0.f; g_bn2[i] = 0.f; }
}

// ---------------- degree count (edge_index is INT32: jax default) ---------
__global__ void k_count(const int* __restrict__ ei) {
    int i = blockIdx.x * blockDim.x + threadIdx.x;
    int stride = gridDim.x * blockDim.x;
    for (int e = i; e < NE; e += stride) {
        int d = ei[NE + e];
        atomicAdd(&g_degcnt[d], 1);
    }
}

// ---------------- prefix scan (3 kernels) ---------------------------------
__global__ void k_scanA() {
    __shared__ int sm[TILE];
    int t = threadIdx.x;
    int i = blockIdx.x * TILE + t;
    int v = (i < NN) ? g_degcnt[i] : 0;
    sm[t] = v;
    __syncthreads();
    #pragma unroll
    for (int off = 1; off < TILE; off <<= 1) {
        int add = (t >= off) ? sm[t - off] : 0;
        __syncthreads();
        sm[t] += add;
        __syncthreads();
    }
    if (i < NN) g_incl[i] = sm[t];
    if (t == TILE - 1) g_tilesum[blockIdx.x] = sm[t];
}

__global__ void k_scanB() {
    __shared__ int sm[128];
    int t = threadIdx.x;
    sm[t] = (t < NTILES) ? g_tilesum[t] : 0;
    __syncthreads();
    if (t == 0) {
        int acc = 0;
        for (int i = 0; i < NTILES; i++) { int v = sm[i]; sm[i] = acc; acc += v; }
    }
    __syncthreads();
    if (t < NTILES) g_tilebase[t] = sm[t];
}

__global__ void k_scanC() {
    int i = blockIdx.x * blockDim.x + threadIdx.x;
    int stride = gridDim.x * blockDim.x;
    for (int n = i; n < NN; n += stride) {
        int deg = g_degcnt[n];
        int excl = g_tilebase[n >> 10] + g_incl[n] - deg;
        g_rowptr[n] = excl;
        g_fill[n]   = excl;
        g_dis[n]    = rsqrtf((float)(deg + 1));
    }
    if (i == 0) g_rowptr[NN] = NE;
}

// ---------------- CSR scatter ---------------------------------------------
__global__ void k_scatter(const int* __restrict__ ei) {
    int i = blockIdx.x * blockDim.x + threadIdx.x;
    int stride = gridDim.x * blockDim.x;
    for (int e = i; e < NE; e += stride) {
        int s = ei[e];
        int d = ei[NE + e];
        float w = g_dis[s] * g_dis[d];
        int pos = atomicAdd(&g_fill[d], 1);
        g_csrc[pos] = s;
        g_cw[pos]   = w;
    }
}

// ---------------- GEMM: out[N,COUT] = act(X)[N,K] @ W[K,COUT] + b ---------
// LAYER==1: X = external arg, no BN on input.
// LAYER==2: X = g_hb, BN(scale1,shift1)+ReLU applied on load.
// LAYER==3: X = g_hb, BN(scale2,shift2)+ReLU applied on load.
// Output always g_ha.
template <int K, int COUT, int LAYER>
__global__ void k_gemm(const float* __restrict__ Xext,
                       const float* __restrict__ W,
                       const float* __restrict__ B) {
    constexpr int TN = 4, TM = 4;
    constexpr int COLT = COUT / TN;       // 16 or 10
    constexpr int ROWT = 16;
    constexpr int RB   = ROWT * TM;       // 64 rows per block
    constexpr int KC   = 32;

    __shared__ __align__(16) float Ws[K * COUT];
    __shared__ float Bs[COUT];
    __shared__ float Xs[RB][KC];

    const float* Xp = (LAYER == 1) ? Xext : g_hb;
    const float* scale = (LAYER == 2) ? g_sc1 : g_sc2;
    const float* shift = (LAYER == 2) ? g_sh1 : g_sh2;
    float* out = g_ha;

    const int tid  = threadIdx.x;
    const int colt = tid % COLT;
    const int rowt = tid / COLT;
    const int rowBase = blockIdx.x * RB;
    const int nthreads = COLT * ROWT;

    for (int idx = tid; idx < K * COUT; idx += nthreads) Ws[idx] = W[idx];
    for (int idx = tid; idx < COUT; idx += nthreads)     Bs[idx] = B[idx];

    float acc[TM][TN];
    #pragma unroll
    for (int i = 0; i < TM; i++)
        #pragma unroll
        for (int j = 0; j < TN; j++) acc[i][j] = 0.f;

    for (int k0 = 0; k0 < K; k0 += KC) {
        __syncthreads();
        // load X tile (with fused BN+ReLU for layers 2,3)
        for (int idx = tid; idx < RB * KC; idx += nthreads) {
            int r = idx / KC, k = idx % KC;
            int gr = rowBase + r;
            float v = 0.f;
            if (gr < NN) {
                v = Xp[(long)gr * K + k0 + k];
                if (LAYER != 1) {
                    v = fmaxf(fmaf(v, scale[k0 + k], shift[k0 + k]), 0.f);
                }
            }
            Xs[r][k] = v;
        }
        __syncthreads();

        #pragma unroll
        for (int k = 0; k < KC; k++) {
            float4 w4 = *reinterpret_cast<const float4*>(&Ws[(k0 + k) * COUT + colt * TN]);
            float xr[TM];
            #pragma unroll
            for (int i = 0; i < TM; i++) xr[i] = Xs[rowt * TM + i][k];
            #pragma unroll
            for (int i = 0; i < TM; i++) {
                acc[i][0] = fmaf(xr[i], w4.x, acc[i][0]);
                acc[i][1] = fmaf(xr[i], w4.y, acc[i][1]);
                acc[i][2] = fmaf(xr[i], w4.z, acc[i][2]);
                acc[i][3] = fmaf(xr[i], w4.w, acc[i][3]);
            }
        }
    }

    float4 b4 = *reinterpret_cast<const float4*>(&Bs[colt * TN]);
    #pragma unroll
    for (int i = 0; i < TM; i++) {
        int gr = rowBase + rowt * TM + i;
        if (gr < NN) {
            float4 o;
            o.x = acc[i][0] + b4.x;
            o.y = acc[i][1] + b4.y;
            o.z = acc[i][2] + b4.z;
            o.w = acc[i][3] + b4.w;
            *reinterpret_cast<float4*>(&out[(long)gr * COUT + colt * TN]) = o;
        }
    }
}

// ---------------- aggregation: one warp per node, atomic-free --------------
// out[n] = selfnorm[n]*h[n] + sum_{edges into n} w * h[src]
// LAYER 1,2: h=g_ha, out=g_hb, BN stats accumulated (C=64).
// LAYER 3:   h=g_ha, out=external (C=40), no stats.
template <int C, int LAYER>
__global__ void k_agg(float* __restrict__ outext) {
    const float* __restrict__ h = g_ha;
    float* out = (LAYER == 3) ? outext : g_hb;
    float* bnacc = (LAYER == 1) ? g_bn1 : g_bn2;

    const int lane = threadIdx.x & 31;
    const int warp = threadIdx.x >> 5;
    const int wpb  = blockDim.x >> 5;
    const int nwarps = gridDim.x * wpb;
    const int gw = blockIdx.x * wpb + warp;
    const int c0 = lane;
    const int c1 = lane + 32;

    float s0 = 0.f, q0 = 0.f, s1 = 0.f, q1 = 0.f;

    for (int node = gw; node < NN; node += nwarps) {
        float dn = g_dis[node];
        float selfn = dn * dn;               // 1/deg
        float a0 = h[(long)node * C + c0] * selfn;
        float a1 = (c1 < C) ? h[(long)node * C + c1] * selfn : 0.f;
        int beg = g_rowptr[node];
        int end = g_rowptr[node + 1];
        for (int j = beg; j < end; j++) {
            int s  = __ldg(&g_csrc[j]);
            float w = __ldg(&g_cw[j]);
            a0 = fmaf(w, __ldg(&h[(long)s * C + c0]), a0);
            if (c1 < C) a1 = fmaf(w, __ldg(&h[(long)s * C + c1]), a1);
        }
        out[(long)node * C + c0] = a0;
        if (c1 < C) out[(long)node * C + c1] = a1;
        if (LAYER != 3) {
            s0 += a0; q0 += a0 * a0;
            s1 += a1; q1 += a1 * a1;
        }
    }

    if (LAYER != 3) {
        __shared__ float ss[64], sq[64];
        if (threadIdx.x < 64) { ss[threadIdx.x] = 0.f; sq[threadIdx.x] = 0.f; }
        __syncthreads();
        atomicAdd(&ss[c0], s0); atomicAdd(&sq[c0], q0);
        atomicAdd(&ss[c1], s1); atomicAdd(&sq[c1], q1);
        __syncthreads();
        if (threadIdx.x < 64) {
            atomicAdd(&bnacc[threadIdx.x],      ss[threadIdx.x]);
            atomicAdd(&bnacc[64 + threadIdx.x], sq[threadIdx.x]);
        }
    }
}

// ---------------- BN finalize: scale/shift from accumulated stats ----------
template <int STAGE>
__global__ void k_bnfin(const float* __restrict__ g, const float* __restrict__ be) {
    const float* acc = (STAGE == 1) ? g_bn1 : g_bn2;
    float* sc = (STAGE == 1) ? g_sc1 : g_sc2;
    float* sh = (STAGE == 1) ? g_sh1 : g_sh2;
    int c = threadIdx.x;
    if (c < HID) {
        float inv_n = 1.0f / (float)NN;
        float mu  = acc[c] * inv_n;
        float var = acc[64 + c] * inv_n - mu * mu;
        float inv = rsqrtf(var + BN_EPS);
        float s = g[c] * inv;
        sc[c] = s;
        sh[c] = fmaf(-mu, s, be[c]);
    }
}

// ---------------- launch ----------------------------------------------------
extern "C" void kernel_launch(void* const* d_in, const int* in_sizes, int n_in,
                              void* d_out, int out_size) {
    const float* x  = (const float*)d_in[0];
    const int*   ei = (const int*)d_in[1];     // int32! (jax default, no x64)
    const float* W1 = (const float*)d_in[2];
    const float* b1 = (const float*)d_in[3];
    const float* g1 = (const float*)d_in[4];
    const float* be1= (const float*)d_in[5];
    const float* W2 = (const float*)d_in[6];
    const float* b2 = (const float*)d_in[7];
    const float* g2 = (const float*)d_in[8];
    const float* be2= (const float*)d_in[9];
    const float* W3 = (const float*)d_in[10];
    const float* b3 = (const float*)d_in[11];
    float* out = (float*)d_out;

    // graph construction (CSR by dst) + norms
    k_init<<<512, 256>>>();
    k_count<<<2048, 256>>>(ei);
    k_scanA<<<NTILES, TILE>>>();
    k_scanB<<<1, 128>>>();
    k_scanC<<<392, 256>>>();
    k_scatter<<<2048, 256>>>(ei);

    const int gemm_grid = (NN + 63) / 64;   // 1563
    const int agg_blocks = 1480;            // 10 per SM, 8 warps each

    // layer 1
    k_gemm<128, 64, 1><<<gemm_grid, 256>>>(x, W1, b1);
    k_agg<64, 1><<<agg_blocks, 256>>>(nullptr);
    k_bnfin<1><<<1, 64>>>(g1, be1);

    // layer 2 (BN1+ReLU fused into GEMM input load)
    k_gemm<64, 64, 2><<<gemm_grid, 256>>>(nullptr, W2, b2);
    k_agg<64, 2><<<agg_blocks, 256>>>(nullptr);
    k_bnfin<2><<<1, 64>>>(g2, be2);

    // layer 3 (BN2+ReLU fused into GEMM input load), C_out = 40
    k_gemm<64, 40, 3><<<gemm_grid, 160>>>(nullptr, W3, b3);
    k_agg<40, 3><<<agg_blocks, 256>>>(out);
}

// round 6
// speedup vs baseline: 1.0759x; 1.0759x over previous
#include <cuda_runtime.h>

// Problem constants
#define NN 100000
#define NE 1600000
constexpr float BN_EPS = 1e-5f;

constexpr int TILE = 1024;
constexpr int NTILES = (NN + TILE - 1) / TILE;   // 98

// ---------------- scratch (static device globals; no runtime alloc) -------
__device__ int   g_degcnt[NN];
__device__ float g_dis[NN];
__device__ int   g_rowptr[NN + 1];
__device__ int   g_fill[NN];
__device__ int   g_incl[NN];
__device__ int   g_tilesum[128];
__device__ int   g_tilebase[128];
__device__ int   g_csrc[NE];
__device__ float g_cw[NE];
__device__ __align__(16) float g_ha[NN * 64];  // gemm outputs (all layers)
__device__ __align__(16) float g_hb[NN * 64];  // agg outputs (layers 1,2)
__device__ float g_bn1[128];                   // [0:64) sum, [64:128) sumsq
__device__ float g_bn2[128];

// ---------------- init ----------------------------------------------------
__global__ void k_init() {
    int i = blockIdx.x * blockDim.x + threadIdx.x;
    int stride = gridDim.x * blockDim.x;
    for (int j = i; j < NN; j += stride) g_degcnt[j] = 0;
    if (i < 128) { g_bn1[i] = 0.f; g_bn2[i] = 0.f; }
}

// ---------------- degree count (edge_index is int32) ----------------------
__global__ void k_count(const int* __restrict__ ei) {
    int i = blockIdx.x * blockDim.x + threadIdx.x;
    int stride = gridDim.x * blockDim.x;
    for (int e = i; e < NE; e += stride) {
        int d = ei[NE + e];
        atomicAdd(&g_degcnt[d], 1);
    }
}

// ---------------- prefix scan (3 kernels) ---------------------------------
__global__ void k_scanA() {
    __shared__ int sm[TILE];
    int t = threadIdx.x;
    int i = blockIdx.x * TILE + t;
    int v = (i < NN) ? g_degcnt[i] : 0;
    sm[t] = v;
    __syncthreads();
    #pragma unroll
    for (int off = 1; off < TILE; off <<= 1) {
        int add = (t >= off) ? sm[t - off] : 0;
        __syncthreads();
        sm[t] += add;
        __syncthreads();
    }
    if (i < NN) g_incl[i] = sm[t];
    if (t == TILE - 1) g_tilesum[blockIdx.x] = sm[t];
}

__global__ void k_scanB() {
    __shared__ int sm[128];
    int t = threadIdx.x;
    sm[t] = (t < NTILES) ? g_tilesum[t] : 0;
    __syncthreads();
    if (t == 0) {
        int acc = 0;
        for (int i = 0; i < NTILES; i++) { int v = sm[i]; sm[i] = acc; acc += v; }
    }
    __syncthreads();
    if (t < NTILES) g_tilebase[t] = sm[t];
}

__global__ void k_scanC() {
    int i = blockIdx.x * blockDim.x + threadIdx.x;
    int stride = gridDim.x * blockDim.x;
    for (int n = i; n < NN; n += stride) {
        int deg = g_degcnt[n];
        int excl = g_tilebase[n >> 10] + g_incl[n] - deg;
        g_rowptr[n] = excl;
        g_fill[n]   = excl;
        g_dis[n]    = rsqrtf((float)(deg + 1));
    }
    if (i == 0) g_rowptr[NN] = NE;
}

// ---------------- CSR scatter ---------------------------------------------
__global__ void k_scatter(const int* __restrict__ ei) {
    int i = blockIdx.x * blockDim.x + threadIdx.x;
    int stride = gridDim.x * blockDim.x;
    for (int e = i; e < NE; e += stride) {
        int s = ei[e];
        int d = ei[NE + e];
        float w = g_dis[s] * g_dis[d];
        int pos = atomicAdd(&g_fill[d], 1);
        g_csrc[pos] = s;
        g_cw[pos]   = w;
    }
}

// ---------------- f32x2 helpers --------------------------------------------
__device__ __forceinline__ unsigned long long pack2(float v) {
    float2 t = make_float2(v, v);
    return *reinterpret_cast<unsigned long long*>(&t);
}
__device__ __forceinline__ void ffma2(unsigned long long& d,
                                      unsigned long long a,
                                      unsigned long long b) {
    asm("fma.rn.f32x2 %0, %1, %2, %0;" : "+l"(d) : "l"(a), "l"(b));
}
__device__ __forceinline__ float2 unpack2(unsigned long long v) {
    return *reinterpret_cast<float2*>(&v);
}

// ---------------- GEMM: out[N,COUT] = act(X)[N,K] @ W[K,COUT] + b ---------
// LAYER==1: X = external, no BN. LAYER==2/3: X = g_hb, BN+ReLU fused on load
// (BN scale/shift computed per-block from global accumulators). Output g_ha.
template <int K, int COUT, int LAYER>
__global__ void k_gemm(const float* __restrict__ Xext,
                       const float* __restrict__ W,
                       const float* __restrict__ Bb,
                       const float* __restrict__ gamma,
                       const float* __restrict__ beta) {
    constexpr int TN = 4, TM = 4;
    constexpr int COLT = COUT / TN;       // 16 or 10
    constexpr int ROWT = 16;
    constexpr int RB   = ROWT * TM;       // 64 rows per block
    constexpr int KC   = 32;

    __shared__ __align__(16) float Ws[K * COUT];
    __shared__ __align__(16) float Bs[COUT];
    __shared__ float Xs[RB][KC];
    __shared__ float sSc[64], sSh[64];

    const float* Xp = (LAYER == 1) ? Xext : g_hb;
    float* out = g_ha;

    const int tid  = threadIdx.x;
    const int colt = tid % COLT;
    const int rowt = tid / COLT;
    const int rowBase = blockIdx.x * RB;
    const int nthreads = COLT * ROWT;

    for (int idx = tid; idx < K * COUT; idx += nthreads) Ws[idx] = W[idx];
    for (int idx = tid; idx < COUT; idx += nthreads)     Bs[idx] = Bb[idx];

    if (LAYER != 1) {
        // BN finalize per-block (redundant but cheap): K == 64 here
        if (tid < K) {
            const float* acc = (LAYER == 2) ? g_bn1 : g_bn2;
            float inv_n = 1.0f / (float)NN;
            float mu  = acc[tid] * inv_n;
            float var = acc[64 + tid] * inv_n - mu * mu;
            float inv = rsqrtf(var + BN_EPS);
            float s = gamma[tid] * inv;
            sSc[tid] = s;
            sSh[tid] = fmaf(-mu, s, beta[tid]);
        }
    }

    unsigned long long a01[TM], a23[TM];
    #pragma unroll
    for (int i = 0; i < TM; i++) { a01[i] = 0ull; a23[i] = 0ull; }

    for (int k0 = 0; k0 < K; k0 += KC) {
        __syncthreads();
        for (int idx = tid; idx < RB * KC; idx += nthreads) {
            int r = idx / KC, k = idx % KC;
            int gr = rowBase + r;
            float v = 0.f;
            if (gr < NN) {
                v = Xp[(long)gr * K + k0 + k];
                if (LAYER != 1)
                    v = fmaxf(fmaf(v, sSc[k0 + k], sSh[k0 + k]), 0.f);
            }
            Xs[r][k] = v;
        }
        __syncthreads();

        #pragma unroll
        for (int k = 0; k < KC; k++) {
            const unsigned long long* wp =
                reinterpret_cast<const unsigned long long*>(&Ws[(k0 + k) * COUT + colt * TN]);
            unsigned long long w01 = wp[0];
            unsigned long long w23 = wp[1];
            #pragma unroll
            for (int i = 0; i < TM; i++) {
                unsigned long long xx = pack2(Xs[rowt * TM + i][k]);
                ffma2(a01[i], xx, w01);
                ffma2(a23[i], xx, w23);
            }
        }
    }

    float4 b4 = *reinterpret_cast<const float4*>(&Bs[colt * TN]);
    #pragma unroll
    for (int i = 0; i < TM; i++) {
        int gr = rowBase + rowt * TM + i;
        if (gr < NN) {
            float2 p01 = unpack2(a01[i]);
            float2 p23 = unpack2(a23[i]);
            float4 o;
            o.x = p01.x + b4.x;
            o.y = p01.y + b4.y;
            o.z = p23.x + b4.z;
            o.w = p23.y + b4.w;
            *reinterpret_cast<float4*>(&out[(long)gr * COUT + colt * TN]) = o;
        }
    }
}

// ---------------- aggregation C=64: float2 lanes, unroll-4, BN stats -------
template <int LAYER>
__global__ void k_agg64() {
    const float2* __restrict__ h2 = reinterpret_cast<const float2*>(g_ha);
    float2* out2 = reinterpret_cast<float2*>(g_hb);
    float* bnacc = (LAYER == 1) ? g_bn1 : g_bn2;

    const int lane = threadIdx.x & 31;
    const int warp = threadIdx.x >> 5;
    const int wpb  = blockDim.x >> 5;
    const int nwarps = gridDim.x * wpb;
    const int gw = blockIdx.x * wpb + warp;

    float sx = 0.f, sy = 0.f, qx = 0.f, qy = 0.f;

    for (int node = gw; node < NN; node += nwarps) {
        float dn = g_dis[node];
        float selfn = dn * dn;                 // 1/deg
        float2 a = h2[node * 32 + lane];
        a.x *= selfn; a.y *= selfn;
        float2 b = make_float2(0.f, 0.f);      // second chain

        int j   = g_rowptr[node];
        int end = g_rowptr[node + 1];
        for (; j + 3 < end; j += 4) {
            int   s0 = __ldg(&g_csrc[j]),   s1 = __ldg(&g_csrc[j+1]);
            int   s2 = __ldg(&g_csrc[j+2]), s3 = __ldg(&g_csrc[j+3]);
            float w0 = __ldg(&g_cw[j]),     w1 = __ldg(&g_cw[j+1]);
            float w2 = __ldg(&g_cw[j+2]),   w3 = __ldg(&g_cw[j+3]);
            float2 v0 = __ldg(&h2[s0 * 32 + lane]);
            float2 v1 = __ldg(&h2[s1 * 32 + lane]);
            float2 v2 = __ldg(&h2[s2 * 32 + lane]);
            float2 v3 = __ldg(&h2[s3 * 32 + lane]);
            a.x = fmaf(w0, v0.x, a.x); a.y = fmaf(w0, v0.y, a.y);
            b.x = fmaf(w1, v1.x, b.x); b.y = fmaf(w1, v1.y, b.y);
            a.x = fmaf(w2, v2.x, a.x); a.y = fmaf(w2, v2.y, a.y);
            b.x = fmaf(w3, v3.x, b.x); b.y = fmaf(w3, v3.y, b.y);
        }
        for (; j < end; j++) {
            int   s = __ldg(&g_csrc[j]);
            float w = __ldg(&g_cw[j]);
            float2 v = __ldg(&h2[s * 32 + lane]);
            a.x = fmaf(w, v.x, a.x); a.y = fmaf(w, v.y, a.y);
        }
        a.x += b.x; a.y += b.y;
        out2[node * 32 + lane] = a;
        sx += a.x; sy += a.y;
        qx += a.x * a.x; qy += a.y * a.y;
    }

    __shared__ float ss[64], sq[64];
    if (threadIdx.x < 64) { ss[threadIdx.x] = 0.f; sq[threadIdx.x] = 0.f; }
    __syncthreads();
    atomicAdd(&ss[2 * lane],     sx);
    atomicAdd(&ss[2 * lane + 1], sy);
    atomicAdd(&sq[2 * lane],     qx);
    atomicAdd(&sq[2 * lane + 1], qy);
    __syncthreads();
    if (threadIdx.x < 64) {
        atomicAdd(&bnacc[threadIdx.x],      ss[threadIdx.x]);
        atomicAdd(&bnacc[64 + threadIdx.x], sq[threadIdx.x]);
    }
}

// ---------------- aggregation C=40 (final layer, output external) ----------
__global__ void k_agg40(float* __restrict__ out) {
    constexpr int C = 40;
    const float* __restrict__ h = g_ha;

    const int lane = threadIdx.x & 31;
    const int warp = threadIdx.x >> 5;
    const int wpb  = blockDim.x >> 5;
    const int nwarps = gridDim.x * wpb;
    const int gw = blockIdx.x * wpb + warp;
    const int c0 = lane;
    const int c1 = lane + 32;
    const bool has1 = (c1 < C);

    for (int node = gw; node < NN; node += nwarps) {
        float dn = g_dis[node];
        float selfn = dn * dn;
        float a0 = h[(long)node * C + c0] * selfn;
        float a1 = has1 ? h[(long)node * C + c1] * selfn : 0.f;
        float b0 = 0.f, b1 = 0.f;

        int j   = g_rowptr[node];
        int end = g_rowptr[node + 1];
        for (; j + 1 < end; j += 2) {
            int   s0 = __ldg(&g_csrc[j]),   s1 = __ldg(&g_csrc[j+1]);
            float w0 = __ldg(&g_cw[j]),     w1 = __ldg(&g_cw[j+1]);
            float u0 = __ldg(&h[(long)s0 * C + c0]);
            float u1 = __ldg(&h[(long)s1 * C + c0]);
            a0 = fmaf(w0, u0, a0);
            b0 = fmaf(w1, u1, b0);
            if (has1) {
                float t0 = __ldg(&h[(long)s0 * C + c1]);
                float t1 = __ldg(&h[(long)s1 * C + c1]);
                a1 = fmaf(w0, t0, a1);
                b1 = fmaf(w1, t1, b1);
            }
        }
        for (; j < end; j++) {
            int   s = __ldg(&g_csrc[j]);
            float w = __ldg(&g_cw[j]);
            a0 = fmaf(w, __ldg(&h[(long)s * C + c0]), a0);
            if (has1) a1 = fmaf(w, __ldg(&h[(long)s * C + c1]), a1);
        }
        out[(long)node * C + c0] = a0 + b0;
        if (has1) out[(long)node * C + c1] = a1 + b1;
    }
}

// ---------------- launch ----------------------------------------------------
extern "C" void kernel_launch(void* const* d_in, const int* in_sizes, int n_in,
                              void* d_out, int out_size) {
    const float* x  = (const float*)d_in[0];
    const int*   ei = (const int*)d_in[1];     // int32 (jax default)
    const float* W1 = (const float*)d_in[2];
    const float* b1 = (const float*)d_in[3];
    const float* g1 = (const float*)d_in[4];
    const float* be1= (const float*)d_in[5];
    const float* W2 = (const float*)d_in[6];
    const float* b2 = (const float*)d_in[7];
    const float* g2 = (const float*)d_in[8];
    const float* be2= (const float*)d_in[9];
    const float* W3 = (const float*)d_in[10];
    const float* b3 = (const float*)d_in[11];
    float* out = (float*)d_out;

    // graph construction (CSR by dst) + norms
    k_init<<<512, 256>>>();
    k_count<<<2048, 256>>>(ei);
    k_scanA<<<NTILES, TILE>>>();
    k_scanB<<<1, 128>>>();
    k_scanC<<<392, 256>>>();
    k_scatter<<<2048, 256>>>(ei);

    const int gemm_grid = (NN + 63) / 64;   // 1563
    const int agg_blocks = 1480;            // 10 per SM, 8 warps each

    // layer 1
    k_gemm<128, 64, 1><<<gemm_grid, 256>>>(x, W1, b1, nullptr, nullptr);
    k_agg64<1><<<agg_blocks, 256>>>();

    // layer 2 (BN1+ReLU fused into GEMM input load, bnfin fused per-block)
    k_gemm<64, 64, 2><<<gemm_grid, 256>>>(nullptr, W2, b2, g1, be1);
    k_agg64<2><<<agg_blocks, 256>>>();

    // layer 3 (BN2+ReLU fused), C_out = 40
    k_gemm<64, 40, 3><<<gemm_grid, 160>>>(nullptr, W3, b3, g2, be2);
    k_agg40<<<agg_blocks, 256>>>(out);
}

// round 7
// speedup vs baseline: 1.2095x; 1.1242x over previous
#include <cuda_runtime.h>

// Problem constants
#define NN 100000
#define NE 1600000
constexpr float BN_EPS = 1e-5f;

constexpr int TILE = 1024;
constexpr int NTILES_SCAN = (NN + TILE - 1) / TILE;   // 98
constexpr int NT_GEMM = (NN + 63) / 64;               // 1563 row tiles

// ---------------- scratch (static device globals; zero-initialized) -------
__device__ int   g_degcnt[NN];        // zeroed at load; re-zeroed by k_scatter
__device__ float g_dis[NN];
__device__ int   g_rowptr[NN + 1];
__device__ int   g_fill[NN];
__device__ int   g_incl[NN];
__device__ int   g_tilesum[128];
__device__ int   g_tilebase[128];
__device__ __align__(16) int2  g_cedge[NE];    // {src, float_bits(w)}
__device__ __align__(16) float g_ha[NN * 64];  // gemm outputs
__device__ __align__(16) float g_hb[NN * 64];  // agg outputs (layers 1,2)
__device__ float g_bn1[128];          // zeroed at load; re-zeroed by k_agg40
__device__ float g_bn2[128];

// ---------------- degree count (edge_index is int32) ----------------------
__global__ void k_count(const int* __restrict__ ei) {
    int i = blockIdx.x * blockDim.x + threadIdx.x;
    int stride = gridDim.x * blockDim.x;
    for (int e = i; e < NE; e += stride) {
        int d = ei[NE + e];
        atomicAdd(&g_degcnt[d], 1);
    }
}

// ---------------- prefix scan (3 kernels) ---------------------------------
__global__ void k_scanA() {
    __shared__ int sm[TILE];
    int t = threadIdx.x;
    int i = blockIdx.x * TILE + t;
    int v = (i < NN) ? g_degcnt[i] : 0;
    sm[t] = v;
    __syncthreads();
    #pragma unroll
    for (int off = 1; off < TILE; off <<= 1) {
        int add = (t >= off) ? sm[t - off] : 0;
        __syncthreads();
        sm[t] += add;
        __syncthreads();
    }
    if (i < NN) g_incl[i] = sm[t];
    if (t == TILE - 1) g_tilesum[blockIdx.x] = sm[t];
}

__global__ void k_scanB() {
    __shared__ int sm[128];
    int t = threadIdx.x;
    sm[t] = (t < NTILES_SCAN) ? g_tilesum[t] : 0;
    __syncthreads();
    if (t == 0) {
        int acc = 0;
        for (int i = 0; i < NTILES_SCAN; i++) { int v = sm[i]; sm[i] = acc; acc += v; }
    }
    __syncthreads();
    if (t < NTILES_SCAN) g_tilebase[t] = sm[t];
}

__global__ void k_scanC() {
    int i = blockIdx.x * blockDim.x + threadIdx.x;
    int stride = gridDim.x * blockDim.x;
    for (int n = i; n < NN; n += stride) {
        int deg = g_degcnt[n];
        int excl = g_tilebase[n >> 10] + g_incl[n] - deg;
        g_rowptr[n] = excl;
        g_fill[n]   = excl;
        g_dis[n]    = rsqrtf((float)(deg + 1));
    }
    if (i == 0) g_rowptr[NN] = NE;
}

// ---------------- CSR scatter (packed edges) + degcnt reset ---------------
__global__ void k_scatter(const int* __restrict__ ei) {
    int i = blockIdx.x * blockDim.x + threadIdx.x;
    int stride = gridDim.x * blockDim.x;
    for (int e = i; e < NE; e += stride) {
        int s = ei[e];
        int d = ei[NE + e];
        float w = g_dis[s] * g_dis[d];
        int pos = atomicAdd(&g_fill[d], 1);
        g_cedge[pos] = make_int2(s, __float_as_int(w));
    }
    // reset degcnt for the next replay (no longer read this replay)
    for (int n = i; n < NN; n += stride) g_degcnt[n] = 0;
}

// ---------------- f32x2 helper ---------------------------------------------
__device__ __forceinline__ void ffma2(unsigned long long& d,
                                      unsigned long long a,
                                      unsigned long long b) {
    asm("fma.rn.f32x2 %0, %1, %2, %0;" : "+l"(d) : "l"(a), "l"(b));
}

// ---------------- persistent GEMM: out = act(X)[N,K] @ W[K,COUT] + b ------
// LAYER==1: X = external, no BN. LAYER==2/3: X = g_hb, BN+ReLU fused on load.
// Output g_ha. Duplicated-X shared tile so inner loop is pure LDS.64/LDS.128
// + FFMA2 (13 issue slots / 32 FMAs).
template <int K, int COUT, int LAYER>
__global__ void __launch_bounds__(COUT * 4) k_gemm(
        const float* __restrict__ Xext,
        const float* __restrict__ W,
        const float* __restrict__ Bb,
        const float* __restrict__ gamma,
        const float* __restrict__ beta) {
    constexpr int TN = 4, TM = 4;
    constexpr int COLT = COUT / TN;       // 16 or 10
    constexpr int ROWT = 16;
    constexpr int RB   = ROWT * TM;       // 64 rows per tile
    constexpr int KC   = 32;
    constexpr int NTH  = COLT * ROWT;

    __shared__ __align__(16) float  Ws[K * COUT];
    __shared__ __align__(16) float  Bs[COUT];
    __shared__ __align__(16) float2 Xs2[RB][KC + 1];   // duplicated, padded
    __shared__ float sSc[64], sSh[64];

    const float* Xp = (LAYER == 1) ? Xext : g_hb;
    float* out = g_ha;

    const int tid  = threadIdx.x;
    const int colt = tid % COLT;
    const int rowt = tid / COLT;

    // one-time staging (persistent)
    for (int idx = tid; idx < K * COUT; idx += NTH) Ws[idx] = W[idx];
    for (int idx = tid; idx < COUT; idx += NTH)     Bs[idx] = Bb[idx];
    if (LAYER != 1) {
        if (tid < K) {   // K == 64 for layers 2,3
            const float* acc = (LAYER == 2) ? g_bn1 : g_bn2;
            float inv_n = 1.0f / (float)NN;
            float mu  = acc[tid] * inv_n;
            float var = acc[64 + tid] * inv_n - mu * mu;
            float inv = rsqrtf(var + BN_EPS);
            float s = gamma[tid] * inv;
            sSc[tid] = s;
            sSh[tid] = fmaf(-mu, s, beta[tid]);
        }
    }
    __syncthreads();

    for (int tile = blockIdx.x; tile < NT_GEMM; tile += gridDim.x) {
        const int rowBase = tile * RB;

        unsigned long long a01[TM], a23[TM];
        #pragma unroll
        for (int i = 0; i < TM; i++) { a01[i] = 0ull; a23[i] = 0ull; }

        for (int k0 = 0; k0 < K; k0 += KC) {
            __syncthreads();
            // stage 64x32 X tile as duplicated float2 (with fused BN+ReLU)
            for (int idx = tid; idx < RB * KC / 4; idx += NTH) {
                int r  = idx >> 3;          // /8 float4s per row-chunk
                int c4 = idx & 7;           // which float4 in the 32-col chunk
                int gr = rowBase + r;
                float4 v = make_float4(0.f, 0.f, 0.f, 0.f);
                if (gr < NN)
                    v = *reinterpret_cast<const float4*>(&Xp[(long)gr * K + k0 + c4 * 4]);
                if (LAYER != 1) {
                    int kk = k0 + c4 * 4;
                    v.x = fmaxf(fmaf(v.x, sSc[kk    ], sSh[kk    ]), 0.f);
                    v.y = fmaxf(fmaf(v.y, sSc[kk + 1], sSh[kk + 1]), 0.f);
                    v.z = fmaxf(fmaf(v.z, sSc[kk + 2], sSh[kk + 2]), 0.f);
                    v.w = fmaxf(fmaf(v.w, sSc[kk + 3], sSh[kk + 3]), 0.f);
                }
                Xs2[r][c4 * 4    ] = make_float2(v.x, v.x);
                Xs2[r][c4 * 4 + 1] = make_float2(v.y, v.y);
                Xs2[r][c4 * 4 + 2] = make_float2(v.z, v.z);
                Xs2[r][c4 * 4 + 3] = make_float2(v.w, v.w);
            }
            __syncthreads();

            #pragma unroll
            for (int k = 0; k < KC; k++) {
                ulonglong2 w2 = *reinterpret_cast<const ulonglong2*>(
                    &Ws[(k0 + k) * COUT + colt * TN]);
                #pragma unroll
                for (int i = 0; i < TM; i++) {
                    unsigned long long xx = *reinterpret_cast<const unsigned long long*>(
                        &Xs2[rowt * TM + i][k]);
                    ffma2(a01[i], xx, w2.x);
                    ffma2(a23[i], xx, w2.y);
                }
            }
        }

        float4 b4 = *reinterpret_cast<const float4*>(&Bs[colt * TN]);
        #pragma unroll
        for (int i = 0; i < TM; i++) {
            int gr = rowBase + rowt * TM + i;
            if (gr < NN) {
                float2 p01 = *reinterpret_cast<float2*>(&a01[i]);
                float2 p23 = *reinterpret_cast<float2*>(&a23[i]);
                float4 o;
                o.x = p01.x + b4.x;
                o.y = p01.y + b4.y;
                o.z = p23.x + b4.z;
                o.w = p23.y + b4.w;
                *reinterpret_cast<float4*>(&out[(long)gr * COUT + colt * TN]) = o;
            }
        }
    }
}

// ---------------- aggregation C=64: warp/node, packed edges, unroll 8 ------
template <int LAYER>
__global__ void __launch_bounds__(256, 6) k_agg64() {
    const float2* __restrict__ h2 = reinterpret_cast<const float2*>(g_ha);
    float2* out2 = reinterpret_cast<float2*>(g_hb);
    float* bnacc = (LAYER == 1) ? g_bn1 : g_bn2;

    const int lane = threadIdx.x & 31;
    const int warp = threadIdx.x >> 5;
    const int nwarps = gridDim.x * 8;
    const int gw = blockIdx.x * 8 + warp;

    float sx = 0.f, sy = 0.f, qx = 0.f, qy = 0.f;

    for (int node = gw; node < NN; node += nwarps) {
        float dn = g_dis[node];
        float selfn = dn * dn;                 // 1/deg
        float2 a = h2[node * 32 + lane];
        a.x *= selfn; a.y *= selfn;
        float2 b = make_float2(0.f, 0.f);

        int j   = g_rowptr[node];
        int end = g_rowptr[node + 1];

        for (; j + 7 < end; j += 8) {
            int2 e0 = __ldg(&g_cedge[j  ]), e1 = __ldg(&g_cedge[j+1]);
            int2 e2 = __ldg(&g_cedge[j+2]), e3 = __ldg(&g_cedge[j+3]);
            int2 e4 = __ldg(&g_cedge[j+4]), e5 = __ldg(&g_cedge[j+5]);
            int2 e6 = __ldg(&g_cedge[j+6]), e7 = __ldg(&g_cedge[j+7]);
            float2 v0 = __ldg(&h2[e0.x * 32 + lane]);
            float2 v1 = __ldg(&h2[e1.x * 32 + lane]);
            float2 v2 = __ldg(&h2[e2.x * 32 + lane]);
            float2 v3 = __ldg(&h2[e3.x * 32 + lane]);
            float2 v4 = __ldg(&h2[e4.x * 32 + lane]);
            float2 v5 = __ldg(&h2[e5.x * 32 + lane]);
            float2 v6 = __ldg(&h2[e6.x * 32 + lane]);
            float2 v7 = __ldg(&h2[e7.x * 32 + lane]);
            float w0 = __int_as_float(e0.y), w1 = __int_as_float(e1.y);
            float w2 = __int_as_float(e2.y), w3 = __int_as_float(e3.y);
            float w4 = __int_as_float(e4.y), w5 = __int_as_float(e5.y);
            float w6 = __int_as_float(e6.y), w7 = __int_as_float(e7.y);
            a.x = fmaf(w0, v0.x, a.x); a.y = fmaf(w0, v0.y, a.y);
            b.x = fmaf(w1, v1.x, b.x); b.y = fmaf(w1, v1.y, b.y);
            a.x = fmaf(w2, v2.x, a.x); a.y = fmaf(w2, v2.y, a.y);
            b.x = fmaf(w3, v3.x, b.x); b.y = fmaf(w3, v3.y, b.y);
            a.x = fmaf(w4, v4.x, a.x); a.y = fmaf(w4, v4.y, a.y);
            b.x = fmaf(w5, v5.x, b.x); b.y = fmaf(w5, v5.y, b.y);
            a.x = fmaf(w6, v6.x, a.x); a.y = fmaf(w6, v6.y, a.y);
            b.x = fmaf(w7, v7.x, b.x); b.y = fmaf(w7, v7.y, b.y);
        }
        if (j + 3 < end) {
            int2 e0 = __ldg(&g_cedge[j  ]), e1 = __ldg(&g_cedge[j+1]);
            int2 e2 = __ldg(&g_cedge[j+2]), e3 = __ldg(&g_cedge[j+3]);
            float2 v0 = __ldg(&h2[e0.x * 32 + lane]);
            float2 v1 = __ldg(&h2[e1.x * 32 + lane]);
            float2 v2 = __ldg(&h2[e2.x * 32 + lane]);
            float2 v3 = __ldg(&h2[e3.x * 32 + lane]);
            float w0 = __int_as_float(e0.y), w1 = __int_as_float(e1.y);
            float w2 = __int_as_float(e2.y), w3 = __int_as_float(e3.y);
            a.x = fmaf(w0, v0.x, a.x); a.y = fmaf(w0, v0.y, a.y);
            b.x = fmaf(w1, v1.x, b.x); b.y = fmaf(w1, v1.y, b.y);
            a.x = fmaf(w2, v2.x, a.x); a.y = fmaf(w2, v2.y, a.y);
            b.x = fmaf(w3, v3.x, b.x); b.y = fmaf(w3, v3.y, b.y);
            j += 4;
        }
        if (j + 1 < end) {
            int2 e0 = __ldg(&g_cedge[j]), e1 = __ldg(&g_cedge[j+1]);
            float2 v0 = __ldg(&h2[e0.x * 32 + lane]);
            float2 v1 = __ldg(&h2[e1.x * 32 + lane]);
            float w0 = __int_as_float(e0.y), w1 = __int_as_float(e1.y);
            a.x = fmaf(w0, v0.x, a.x); a.y = fmaf(w0, v0.y, a.y);
            b.x = fmaf(w1, v1.x, b.x); b.y = fmaf(w1, v1.y, b.y);
            j += 2;
        }
        if (j < end) {
            int2 e = __ldg(&g_cedge[j]);
            float2 v = __ldg(&h2[e.x * 32 + lane]);
            float w = __int_as_float(e.y);
            a.x = fmaf(w, v.x, a.x); a.y = fmaf(w, v.y, a.y);
        }

        a.x += b.x; a.y += b.y;
        out2[node * 32 + lane] = a;
        sx += a.x; sy += a.y;
        qx += a.x * a.x; qy += a.y * a.y;
    }

    __shared__ float ss[64], sq[64];
    if (threadIdx.x < 64) { ss[threadIdx.x] = 0.f; sq[threadIdx.x] = 0.f; }
    __syncthreads();
    atomicAdd(&ss[2 * lane],     sx);
    atomicAdd(&ss[2 * lane + 1], sy);
    atomicAdd(&sq[2 * lane],     qx);
    atomicAdd(&sq[2 * lane + 1], qy);
    __syncthreads();
    if (threadIdx.x < 64) {
        atomicAdd(&bnacc[threadIdx.x],      ss[threadIdx.x]);
        atomicAdd(&bnacc[64 + threadIdx.x], sq[threadIdx.x]);
    }
}

// ---------------- aggregation C=40 (final, external out) + bn reset --------
__global__ void __launch_bounds__(256, 6) k_agg40(float* __restrict__ out) {
    constexpr int C = 40;
    const float* __restrict__ h = g_ha;

    const int lane = threadIdx.x & 31;
    const int warp = threadIdx.x >> 5;
    const int nwarps = gridDim.x * 8;
    const int gw = blockIdx.x * 8 + warp;
    const int c0 = lane;
    const int c1 = lane + 32;
    const bool has1 = (c1 < C);

    for (int node = gw; node < NN; node += nwarps) {
        float dn = g_dis[node];
        float selfn = dn * dn;
        float a0 = h[(long)node * C + c0] * selfn;
        float a1 = has1 ? h[(long)node * C + c1] * selfn : 0.f;
        float b0 = 0.f, b1 = 0.f;

        int j   = g_rowptr[node];
        int end = g_rowptr[node + 1];
        for (; j + 3 < end; j += 4) {
            int2 e0 = __ldg(&g_cedge[j  ]), e1 = __ldg(&g_cedge[j+1]);
            int2 e2 = __ldg(&g_cedge[j+2]), e3 = __ldg(&g_cedge[j+3]);
            float w0 = __int_as_float(e0.y), w1 = __int_as_float(e1.y);
            float w2 = __int_as_float(e2.y), w3 = __int_as_float(e3.y);
            float u0 = __ldg(&h[(long)e0.x * C + c0]);
            float u1 = __ldg(&h[(long)e1.x * C + c0]);
            float u2 = __ldg(&h[(long)e2.x * C + c0]);
            float u3 = __ldg(&h[(long)e3.x * C + c0]);
            a0 = fmaf(w0, u0, a0); b0 = fmaf(w1, u1, b0);
            a0 = fmaf(w2, u2, a0); b0 = fmaf(w3, u3, b0);
            if (has1) {
                float t0 = __ldg(&h[(long)e0.x * C + c1]);
                float t1 = __ldg(&h[(long)e1.x * C + c1]);
                float t2 = __ldg(&h[(long)e2.x * C + c1]);
                float t3 = __ldg(&h[(long)e3.x * C + c1]);
                a1 = fmaf(w0, t0, a1); b1 = fmaf(w1, t1, b1);
                a1 = fmaf(w2, t2, a1); b1 = fmaf(w3, t3, b1);
            }
        }
        for (; j < end; j++) {
            int2 e = __ldg(&g_cedge[j]);
            float w = __int_as_float(e.y);
            a0 = fmaf(w, __ldg(&h[(long)e.x * C + c0]), a0);
            if (has1) a1 = fmaf(w, __ldg(&h[(long)e.x * C + c1]), a1);
        }
        out[(long)node * C + c0] = a0 + b0;
        if (has1) out[(long)node * C + c1] = a1 + b1;
    }

    // reset BN accumulators for the next replay (already consumed by gemm2/3)
    if (blockIdx.x == 0 && threadIdx.x < 128) {
        g_bn1[threadIdx.x] = 0.f;
        g_bn2[threadIdx.x] = 0.f;
    }
}

// ---------------- launch ----------------------------------------------------
extern "C" void kernel_launch(void* const* d_in, const int* in_sizes, int n_in,
                              void* d_out, int out_size) {
    const float* x  = (const float*)d_in[0];
    const int*   ei = (const int*)d_in[1];     // int32 (jax default)
    const float* W1 = (const float*)d_in[2];
    const float* b1 = (const float*)d_in[3];
    const float* g1 = (const float*)d_in[4];
    const float* be1= (const float*)d_in[5];
    const float* W2 = (const float*)d_in[6];
    const float* b2 = (const float*)d_in[7];
    const float* g2 = (const float*)d_in[8];
    const float* be2= (const float*)d_in[9];
    const float* W3 = (const float*)d_in[10];
    const float* b3 = (const float*)d_in[11];
    float* out = (float*)d_out;

    // graph construction (CSR by dst) + norms
    k_count<<<1184, 256>>>(ei);
    k_scanA<<<NTILES_SCAN, TILE>>>();
    k_scanB<<<1, 128>>>();
    k_scanC<<<392, 256>>>();
    k_scatter<<<1184, 256>>>(ei);

    // layer 1
    k_gemm<128, 64, 1><<<592, 256>>>(x, W1, b1, nullptr, nullptr);
    k_agg64<1><<<888, 256>>>();

    // layer 2 (BN1+ReLU fused into GEMM input load)
    k_gemm<64, 64, 2><<<888, 256>>>(nullptr, W2, b2, g1, be1);
    k_agg64<2><<<888, 256>>>();

    // layer 3 (BN2+ReLU fused), C_out = 40
    k_gemm<64, 40, 3><<<1184, 160>>>(nullptr, W3, b3, g2, be2);
    k_agg40<<<888, 256>>>(out);
}